// round 16
// baseline (speedup 1.0000x reference)
#include <cuda_runtime.h>
#include <cstdint>
#include <cstring>

#define T_STEPS 2048
#define BATCH   8
#define DIMK    1024
#define NST     64
#define M_ROWS  (T_STEPS * BATCH)
#define NCOL    256

#define CHUNK   8
#define NCHUNK  (T_STEPS / CHUNK)   // 256

// 16 MB scratch: projections, layout [t*BATCH+b][ k(0:64) | q(64:128) | v(128:192) | alpha(192:256) ]
__device__ __align__(16) float g_proj[(size_t)M_ROWS * NCOL];
// 1 MB Gram scratch: [b][chunk][ G(64) | H(64) ]
__device__ __align__(16) float g_gram[(size_t)BATCH * NCHUNK * 128];
// 33.5 MB chunk-start states: [b][chunk][row i][e]
__device__ __align__(16) float g_state[(size_t)BATCH * NCHUNK * NST * NST];
// 8.4 MB per-row chunk scalars: [b][chunk][row i][ w(8) | P1..P8(8) ]
__device__ __align__(16) float g_wp[(size_t)BATCH * NCHUNK * NST * 16];
// 2 MB pre-split weights: [sel][n][k] -> (tf32_hi, tf32_lo) pairs
__device__ __align__(16) uint2 g_wsplit[(size_t)4 * NST * DIMK];

union F2U { float2 f2; unsigned long long u; };

__device__ __forceinline__ float2 f2fma(float2 a, float2 b, float2 c) {
    F2U ua, ub, uc, ud; ua.f2 = a; ub.f2 = b; uc.f2 = c;
    asm("fma.rn.f32x2 %0, %1, %2, %3;" : "=l"(ud.u) : "l"(ua.u), "l"(ub.u), "l"(uc.u));
    return ud.f2;
}
__device__ __forceinline__ float2 f2mul(float2 a, float2 b) {
    F2U ua, ub, ud; ua.f2 = a; ub.f2 = b;
    asm("mul.rn.f32x2 %0, %1, %2;" : "=l"(ud.u) : "l"(ua.u), "l"(ub.u));
    return ud.f2;
}
__device__ __forceinline__ float2 f2dup(float a) {
    F2U ud;
    asm("mov.b64 %0, {%1, %1};" : "=l"(ud.u) : "f"(a));
    return ud.f2;
}
__device__ __forceinline__ float sigmoidf_fast(float x) {
    return __fdividef(1.0f, 1.0f + __expf(-x));
}

// ============================================================================
// tf32 helpers
// ============================================================================
__device__ __forceinline__ uint32_t f2tf(float a) {
    uint32_t r;
    asm("cvt.rna.tf32.f32 %0, %1;" : "=r"(r) : "f"(a));
    return r;
}
__device__ __forceinline__ void tf_split(float a, uint32_t& hi, uint32_t& lo) {
    hi = f2tf(a);
    lo = f2tf(__fsub_rn(a, __uint_as_float(hi)));
}
__device__ __forceinline__ void mma_tf32(float (&d)[4], const uint32_t (&a)[4],
                                         const uint32_t (&b)[2]) {
    asm("mma.sync.aligned.m16n8k8.row.col.f32.tf32.tf32.f32 "
        "{%0,%1,%2,%3},{%4,%5,%6,%7},{%8,%9},{%0,%1,%2,%3};"
        : "+f"(d[0]), "+f"(d[1]), "+f"(d[2]), "+f"(d[3])
        : "r"(a[0]), "r"(a[1]), "r"(a[2]), "r"(a[3]), "r"(b[0]), "r"(b[1]));
}

// ============================================================================
// Kernel 0: pre-split all 4 weight matrices into tf32 (hi,lo) pairs.
// ============================================================================
__global__ void __launch_bounds__(256) wsplit_kernel(
    const float* __restrict__ Wk, const float* __restrict__ Wq,
    const float* __restrict__ Wv, const float* __restrict__ Wa)
{
    const int idx = blockIdx.x * 256 + threadIdx.x;   // 0 .. 4*64*1024-1
    const int sel = idx >> 16;
    const int rem = idx & 65535;
    const float* W = (sel == 0) ? Wk : (sel == 1) ? Wq : (sel == 2) ? Wv : Wa;
    uint32_t hi, lo;
    tf_split(W[rem], hi, lo);
    g_wsplit[idx] = make_uint2(hi, lo);
}

// ============================================================================
// Kernel 1: projection GEMM on tensor cores, 3xTF32.
// A path identical to R8; B path reads PRE-SPLIT (hi,lo) pairs -> zero ALU.
// CTA: 256 thr (8 warps), tile 128m x 64n x 32k. Warp: 32m x 32n.
// ============================================================================
#define TBM 128
#define TBN 64
#define TBK 32
#define XS_STRIDE 36
#define WST2 36      // uint2 stride; mod16=4 -> 4g+tg distinct per phase

__global__ void __launch_bounds__(256, 2) proj_tc_kernel(
    const float* __restrict__ x,
    const float* __restrict__ b_alpha)
{
    __shared__ __align__(16) float Xs[TBM * XS_STRIDE];
    __shared__ __align__(16) uint2 Ws2[TBN * WST2];

    const int tid = threadIdx.x;
    const int m0  = blockIdx.x * TBM;
    const int sel = blockIdx.y;

    const int warp  = tid >> 5;
    const int lane  = tid & 31;
    const int g     = lane >> 2;
    const int tg    = lane & 3;
    const int wm    = warp >> 1;
    const int wn    = warp & 1;
    const int am0   = wm * 32 + g;
    const int cn0   = wn * 32 + g;

    // X loader (as R8)
    const int lr0 = tid >> 3;
    const int lc0 = (tid & 7) * 4;
    const float* xp = &x[(size_t)(m0 + lr0) * DIMK + lc0];

    // W loader: 64 rows x 32 uint2 per tile; thread -> row tid>>2, k (tid&3)*8
    const int wrow = tid >> 2;
    const int wcol = (tid & 3) * 8;
    const uint2* wp = &g_wsplit[((size_t)sel * NST + wrow) * DIMK + wcol];

    float acc[2][4][4];
    #pragma unroll
    for (int mt = 0; mt < 2; mt++)
        #pragma unroll
        for (int nt = 0; nt < 4; nt++)
            #pragma unroll
            for (int j = 0; j < 4; j++) acc[mt][nt][j] = 0.f;

    float4 xr[4];
    uint4  wr[4];
    #pragma unroll
    for (int i = 0; i < 4; i++)
        xr[i] = *reinterpret_cast<const float4*>(xp + (size_t)i * 32 * DIMK);
    #pragma unroll
    for (int i = 0; i < 4; i++)
        wr[i] = reinterpret_cast<const uint4*>(wp)[i];

    for (int k0 = 0; k0 < DIMK; k0 += TBK) {
        __syncthreads();
        #pragma unroll
        for (int i = 0; i < 4; i++)
            *reinterpret_cast<float4*>(&Xs[(lr0 + 32 * i) * XS_STRIDE + lc0]) = xr[i];
        #pragma unroll
        for (int i = 0; i < 4; i++)
            reinterpret_cast<uint4*>(&Ws2[wrow * WST2 + wcol])[i] = wr[i];
        __syncthreads();

        if (k0 + TBK < DIMK) {
            #pragma unroll
            for (int i = 0; i < 4; i++)
                xr[i] = *reinterpret_cast<const float4*>(xp + (size_t)i * 32 * DIMK + k0 + TBK);
            #pragma unroll
            for (int i = 0; i < 4; i++)
                wr[i] = reinterpret_cast<const uint4*>(wp + k0 + TBK)[i];
        }

        #pragma unroll
        for (int ks = 0; ks < TBK / 8; ks++) {
            const int kk = ks * 8;

            uint32_t ah[2][4], al[2][4];
            #pragma unroll
            for (int mt = 0; mt < 2; mt++) {
                const int r0 = (am0 + mt * 16) * XS_STRIDE;
                const int r8 = (am0 + mt * 16 + 8) * XS_STRIDE;
                float a0 = Xs[r0 + kk + tg];
                float a1 = Xs[r8 + kk + tg];
                float a2 = Xs[r0 + kk + tg + 4];
                float a3 = Xs[r8 + kk + tg + 4];
                tf_split(a0, ah[mt][0], al[mt][0]);
                tf_split(a1, ah[mt][1], al[mt][1]);
                tf_split(a2, ah[mt][2], al[mt][2]);
                tf_split(a3, ah[mt][3], al[mt][3]);
            }
            uint32_t bh[4][2], bl[4][2];
            #pragma unroll
            for (int nt = 0; nt < 4; nt++) {
                const int c0 = (cn0 + nt * 8) * WST2 + kk + tg;
                uint2 u0 = Ws2[c0];
                uint2 u1 = Ws2[c0 + 4];
                bh[nt][0] = u0.x; bl[nt][0] = u0.y;
                bh[nt][1] = u1.x; bl[nt][1] = u1.y;
            }
            #pragma unroll
            for (int mt = 0; mt < 2; mt++)
                #pragma unroll
                for (int nt = 0; nt < 4; nt++) {
                    mma_tf32(acc[mt][nt], ah[mt], bh[nt]);
                    mma_tf32(acc[mt][nt], al[mt], bh[nt]);
                    mma_tf32(acc[mt][nt], ah[mt], bl[nt]);
                }
        }
    }

    #pragma unroll
    for (int mt = 0; mt < 2; mt++) {
        #pragma unroll
        for (int nt = 0; nt < 4; nt++) {
            const int row = m0 + wm * 32 + mt * 16 + g;
            const int col = wn * 32 + nt * 8 + 2 * tg;
            float c0 = acc[mt][nt][0], c1 = acc[mt][nt][1];
            float c2 = acc[mt][nt][2], c3 = acc[mt][nt][3];
            if (sel == 3) {
                const float ba0 = b_alpha[col], ba1 = b_alpha[col + 1];
                c0 = sigmoidf_fast(c0 + ba0); c1 = sigmoidf_fast(c1 + ba1);
                c2 = sigmoidf_fast(c2 + ba0); c3 = sigmoidf_fast(c3 + ba1);
            }
            *reinterpret_cast<float2*>(&g_proj[(size_t)row * NCOL + sel * 64 + col])
                = make_float2(c0, c1);
            *reinterpret_cast<float2*>(&g_proj[(size_t)(row + 8) * NCOL + sel * 64 + col])
                = make_float2(c2, c3);
        }
    }
}

// ============================================================================
// Kernel 2: Gram precompute. block = one (chunk, batch):
// G[j][t]=k_j.k_t, H[j][t]=k_j.q_t. 128 threads = 128 dots of 64.
// ============================================================================
__global__ void __launch_bounds__(128) gram_kernel()
{
    __shared__ __align__(16) float kq[CHUNK][128];
    const int cb = blockIdx.x;
    const int c  = cb >> 3;
    const int b  = cb & 7;
    const int tid = threadIdx.x;

    const int st  = tid >> 4;
    const int off = (tid & 15) * 8;
    const float* src = &g_proj[((size_t)(c * CHUNK + st) * BATCH + b) * NCOL + off];
    *reinterpret_cast<float4*>(&kq[st][off])     = *reinterpret_cast<const float4*>(src);
    *reinterpret_cast<float4*>(&kq[st][off + 4]) = *reinterpret_cast<const float4*>(src + 4);
    __syncthreads();

    const int m = tid >> 6;          // 0 = G, 1 = H
    const int j = (tid >> 3) & 7;
    const int t = tid & 7;
    const float* kj = &kq[j][0];
    const float* xt = &kq[t][m ? 64 : 0];
    float sum = 0.f;
    #pragma unroll
    for (int e = 0; e < 64; e += 4) {
        float4 kv = *reinterpret_cast<const float4*>(kj + e);
        float4 xv = *reinterpret_cast<const float4*>(xt + e);
        sum = __fmaf_rn(kv.x, xv.x, sum);
        sum = __fmaf_rn(kv.y, xv.y, sum);
        sum = __fmaf_rn(kv.z, xv.z, sum);
        sum = __fmaf_rn(kv.w, xv.w, sum);
    }
    g_gram[((size_t)b * NCHUNK + c) * 128 + m * 64 + j * 8 + t] = sum;
}

// ============================================================================
// Kernel 3: chunked scan (R15 tanh-chain version), recurrence only.
// 16 lanes/row, 2 rows/warp, 256 blocks x 32 threads.
// ============================================================================
#define RS 4
#define SLOT_FLOATS (CHUNK * NCOL + 64)

__device__ __forceinline__ void fetch_chunk(
    const float* gp, const float* gram_b, uint32_t sbase, int cf, int slot, int lane)
{
    uint32_t dst = sbase + (uint32_t)(slot * SLOT_FLOATS) * 4u;
    #pragma unroll
    for (int st = 0; st < CHUNK; st++) {
        const float* src = gp + (size_t)(cf * CHUNK + st) * BATCH * NCOL + lane * 8;
        uint32_t d = dst + (uint32_t)(st * NCOL + lane * 8) * 4u;
        asm volatile(
            "cp.async.ca.shared.global [%0], [%1], 16;\n\t"
            "cp.async.ca.shared.global [%2], [%3], 16;\n\t"
            :: "r"(d), "l"(src), "r"(d + 16u), "l"(src + 4));
    }
    const float* gs = gram_b + (size_t)cf * 128 + lane * 2;
    uint32_t d2 = dst + (uint32_t)(CHUNK * NCOL + lane * 2) * 4u;
    asm volatile("cp.async.ca.shared.global [%0], [%1], 8;" :: "r"(d2), "l"(gs));
    asm volatile("cp.async.commit_group;");
}

__global__ void __launch_bounds__(32) scan_kernel(
    const float* __restrict__ S0,
    const float* __restrict__ d_g,
    const float* __restrict__ b_g,
    float* __restrict__ Sfin)    // [B,N,N]
{
    __shared__ __align__(16) float ring[RS][SLOT_FLOATS];

    const int bx   = blockIdx.x;          // 0..255
    const int b    = bx >> 5;
    const int rg   = bx & 31;
    const int lane = threadIdx.x;
    const int r_   = lane >> 4;
    const int c    = lane & 15;
    const int i    = rg * 2 + r_;

    const float hd = 0.5f * d_g[i];
    const float hb = 0.5f * b_g[i];

    const float* gp     = &g_proj[(size_t)b * NCOL];
    const float* gram_b = &g_gram[(size_t)b * NCHUNK * 128];
    const uint32_t sbase = (uint32_t)__cvta_generic_to_shared(&ring[0][0]);

    float2 s[2];
    {
        float4 v0 = *reinterpret_cast<const float4*>(
            &S0[(size_t)(b * NST + i) * NST + c * 4]);
        s[0] = make_float2(v0.x, v0.y); s[1] = make_float2(v0.z, v0.w);
    }

    #pragma unroll
    for (int d = 0; d < RS - 1; d++)
        fetch_chunk(gp, gram_b, sbase, d, d, lane);

    for (int ch = 0; ch < NCHUNK; ch++) {
        {
            int cf = ch + RS - 1;
            if (cf > NCHUNK - 1) cf = NCHUNK - 1;
            fetch_chunk(gp, gram_b, sbase, cf, (ch + RS - 1) & (RS - 1), lane);
        }
        asm volatile("cp.async.wait_group %0;" :: "n"(RS - 2));
        __syncwarp();

        const float* p = &ring[ch & (RS - 1)][0];

        *reinterpret_cast<float4*>(
            &g_state[(((size_t)b * NCHUNK + ch) * NST + i) * NST + c * 4])
            = make_float4(s[0].x, s[0].y, s[1].x, s[1].y);

        float A[8];
        #pragma unroll
        for (int t = 0; t < 8; t++) {
            float4 kv = *reinterpret_cast<const float4*>(p + t * NCOL + c * 4);
            float2 aa = f2mul(s[0], make_float2(kv.x, kv.y));
            aa = f2fma(s[1], make_float2(kv.z, kv.w), aa);
            A[t] = aa.x + aa.y;
        }
        #pragma unroll
        for (int t = 0; t < 8; t++) {
            A[t] += __shfl_xor_sync(0xffffffffu, A[t], 1);
            A[t] += __shfl_xor_sync(0xffffffffu, A[t], 2);
            A[t] += __shfl_xor_sync(0xffffffffu, A[t], 4);
            A[t] += __shfl_xor_sync(0xffffffffu, A[t], 8);
        }

        float P[9], hdP[8], hcq[8];
        P[0] = 1.f;
        #pragma unroll
        for (int t = 0; t < 8; t++) {
            float al = p[t * NCOL + 192 + i];
            float vv = p[t * NCOL + 128 + i];
            float cvi = (1.f - al) * vv;
            P[t + 1] = P[t] * al;
            float qr;
            asm("rcp.approx.f32 %0, %1;" : "=f"(qr) : "f"(P[t + 1]));
            hdP[t] = hd * P[t];
            hcq[t] = 0.5f * cvi * qr;
        }

        const float* gG = p + CHUNK * NCOL;
        float w[8];
        #pragma unroll
        for (int j = 0; j < 8; j++) {
            float4 g0 = *reinterpret_cast<const float4*>(gG + j * 8);
            float4 g1 = *reinterpret_cast<const float4*>(gG + j * 8 + 4);
            const float gv[8] = { g0.x, g0.y, g0.z, g0.w, g1.x, g1.y, g1.z, g1.w };

            float th;
            asm("tanh.approx.f32 %0, %1;" : "=f"(th) : "f"(__fmaf_rn(hdP[j], A[j], hb)));
            float wj = __fmaf_rn(hcq[j], th, hcq[j]);
            w[j] = wj;
            #pragma unroll
            for (int t2 = j + 1; t2 < 8; t2++)
                A[t2] = __fmaf_rn(wj, gv[t2], A[t2]);
        }

        if (c == 0) {
            float* wp = &g_wp[(((size_t)b * NCHUNK + ch) * NST + i) * 16];
            reinterpret_cast<float4*>(wp)[0] = make_float4(w[0], w[1], w[2], w[3]);
            reinterpret_cast<float4*>(wp)[1] = make_float4(w[4], w[5], w[6], w[7]);
            reinterpret_cast<float4*>(wp)[2] = make_float4(P[1], P[2], P[3], P[4]);
            reinterpret_cast<float4*>(wp)[3] = make_float4(P[5], P[6], P[7], P[8]);
        }

        #pragma unroll
        for (int j = 0; j < 8; j++) {
            float4 kv = *reinterpret_cast<const float4*>(p + j * NCOL + c * 4);
            float2 wj2 = f2dup(w[j]);
            s[0] = f2fma(wj2, make_float2(kv.x, kv.y), s[0]);
            s[1] = f2fma(wj2, make_float2(kv.z, kv.w), s[1]);
        }
        {
            float2 P82 = f2dup(P[8]);
            s[0] = f2mul(P82, s[0]);
            s[1] = f2mul(P82, s[1]);
        }
    }

    *reinterpret_cast<float4*>(&Sfin[(size_t)(b * NST + i) * NST + c * 4])
        = make_float4(s[0].x, s[0].y, s[1].x, s[1].y);
}

// ============================================================================
// Kernel 4: outputs (fully parallel) + fused self-gate.
// ============================================================================
__global__ void __launch_bounds__(256) out_kernel(float* __restrict__ out)
{
    __shared__ __align__(16) float qs[4][CHUNK][64];
    __shared__ __align__(16) float Hs[4][64];

    const int grp = threadIdx.x >> 6;
    const int i   = threadIdx.x & 63;
    const int cb  = blockIdx.x * 4 + grp;
    const int c   = cb >> 3;
    const int b   = cb & 7;

    #pragma unroll
    for (int t = 0; t < CHUNK; t++)
        qs[grp][t][i] = g_proj[((size_t)(c * CHUNK + t) * BATCH + b) * NCOL + 64 + i];
    Hs[grp][i] = g_gram[((size_t)b * NCHUNK + c) * 128 + 64 + i];
    __syncthreads();

    float4 S[16];
    {
        const float4* sp = reinterpret_cast<const float4*>(
            &g_state[(((size_t)b * NCHUNK + c) * NST + i) * NST]);
        #pragma unroll
        for (int e = 0; e < 16; e++) S[e] = sp[e];
    }

    float sq[8];
    #pragma unroll
    for (int t = 0; t < 8; t++) {
        float sum = 0.f;
        #pragma unroll
        for (int e = 0; e < 16; e++) {
            float4 qv = *reinterpret_cast<const float4*>(&qs[grp][t][e * 4]);
            sum = __fmaf_rn(S[e].x, qv.x, sum);
            sum = __fmaf_rn(S[e].y, qv.y, sum);
            sum = __fmaf_rn(S[e].z, qv.z, sum);
            sum = __fmaf_rn(S[e].w, qv.w, sum);
        }
        sq[t] = sum;
    }

    float w[8], Pv[8];
    {
        const float4* wp = reinterpret_cast<const float4*>(
            &g_wp[(((size_t)b * NCHUNK + c) * NST + i) * 16]);
        float4 w0 = wp[0], w1 = wp[1], p0 = wp[2], p1 = wp[3];
        w[0] = w0.x; w[1] = w0.y; w[2] = w0.z; w[3] = w0.w;
        w[4] = w1.x; w[5] = w1.y; w[6] = w1.z; w[7] = w1.w;
        Pv[0] = p0.x; Pv[1] = p0.y; Pv[2] = p0.z; Pv[3] = p0.w;
        Pv[4] = p1.x; Pv[5] = p1.y; Pv[6] = p1.z; Pv[7] = p1.w;
    }

    #pragma unroll
    for (int t = 0; t < 8; t++) {
        float a = sq[t];
        #pragma unroll
        for (int j = 0; j <= t; j++)
            a = __fmaf_rn(w[j], Hs[grp][j * 8 + t], a);
        float o = Pv[t] * a;
        float y = o * o * sigmoidf_fast(o);
        out[((size_t)(c * CHUNK + t) * BATCH + b) * NST + i] = y;
    }
}

// ============================================================================
extern "C" void kernel_launch(void* const* d_in, const int* in_sizes, int n_in,
                              void* d_out, int out_size) {
    const float* x   = (const float*)d_in[0];
    const float* S0  = (const float*)d_in[1];
    const float* Wk  = (const float*)d_in[2];
    const float* Wv  = (const float*)d_in[3];
    const float* Wq  = (const float*)d_in[4];
    const float* Wa  = (const float*)d_in[5];
    const float* ba  = (const float*)d_in[6];
    const float* dg  = (const float*)d_in[7];
    const float* bg  = (const float*)d_in[8];

    float* out  = (float*)d_out;                         // [T,B,N]
    float* Sfin = out + (size_t)T_STEPS * BATCH * NST;   // [B,N,N]

    wsplit_kernel<<<4 * NST * DIMK / 256, 256>>>(Wk, Wq, Wv, Wa);
    dim3 g1(M_ROWS / TBM, 4);
    proj_tc_kernel<<<g1, 256>>>(x, ba);
    gram_kernel<<<NCHUNK * BATCH, 128>>>();
    scan_kernel<<<256, 32>>>(S0, dg, bg, Sfin);
    out_kernel<<<NCHUNK * BATCH / 4, 256>>>(out);
}

// round 17
// speedup vs baseline: 1.1067x; 1.1067x over previous
#include <cuda_runtime.h>
#include <cstdint>
#include <cstring>

#define T_STEPS 2048
#define BATCH   8
#define DIMK    1024
#define NST     64
#define M_ROWS  (T_STEPS * BATCH)
#define NCOL    256

#define CHUNK   8
#define NCHUNK  (T_STEPS / CHUNK)   // 256

// 16 MB scratch: projections, layout [t*BATCH+b][ k(0:64) | q(64:128) | v(128:192) | alpha(192:256) ]
__device__ __align__(16) float g_proj[(size_t)M_ROWS * NCOL];
// 1 MB Gram scratch: [b][chunk][ G(64) | H(64) ]
__device__ __align__(16) float g_gram[(size_t)BATCH * NCHUNK * 128];
// 33.5 MB chunk-start states: [b][chunk][row i][e]
__device__ __align__(16) float g_state[(size_t)BATCH * NCHUNK * NST * NST];
// 8.4 MB per-row chunk scalars: [b][chunk][row i][ w(8) | P1..P8(8) ]
__device__ __align__(16) float g_wp[(size_t)BATCH * NCHUNK * NST * 16];

union F2U { float2 f2; unsigned long long u; };

__device__ __forceinline__ float2 f2fma(float2 a, float2 b, float2 c) {
    F2U ua, ub, uc, ud; ua.f2 = a; ub.f2 = b; uc.f2 = c;
    asm("fma.rn.f32x2 %0, %1, %2, %3;" : "=l"(ud.u) : "l"(ua.u), "l"(ub.u), "l"(uc.u));
    return ud.f2;
}
__device__ __forceinline__ float2 f2mul(float2 a, float2 b) {
    F2U ua, ub, ud; ua.f2 = a; ub.f2 = b;
    asm("mul.rn.f32x2 %0, %1, %2;" : "=l"(ud.u) : "l"(ua.u), "l"(ub.u));
    return ud.f2;
}
__device__ __forceinline__ float2 f2dup(float a) {
    F2U ud;
    asm("mov.b64 %0, {%1, %1};" : "=l"(ud.u) : "f"(a));
    return ud.f2;
}
__device__ __forceinline__ float sigmoidf_fast(float x) {
    return __fdividef(1.0f, 1.0f + __expf(-x));
}

// ============================================================================
// tf32 helpers
// ============================================================================
__device__ __forceinline__ uint32_t f2tf(float a) {
    uint32_t r;
    asm("cvt.rna.tf32.f32 %0, %1;" : "=r"(r) : "f"(a));
    return r;
}
__device__ __forceinline__ void tf_split(float a, uint32_t& hi, uint32_t& lo) {
    hi = f2tf(a);
    lo = f2tf(__fsub_rn(a, __uint_as_float(hi)));
}
__device__ __forceinline__ void mma_tf32(float (&d)[4], const uint32_t (&a)[4],
                                         const uint32_t (&b)[2]) {
    asm("mma.sync.aligned.m16n8k8.row.col.f32.tf32.tf32.f32 "
        "{%0,%1,%2,%3},{%4,%5,%6,%7},{%8,%9},{%0,%1,%2,%3};"
        : "+f"(d[0]), "+f"(d[1]), "+f"(d[2]), "+f"(d[3])
        : "r"(a[0]), "r"(a[1]), "r"(a[2]), "r"(a[3]), "r"(b[0]), "r"(b[1]));
}

// ============================================================================
// Kernel 1: projection GEMM on tensor cores, 3xTF32 (R8/R15 version, 169.9us).
// ============================================================================
#define TBM 128
#define TBN 64
#define TBK 32
#define XS_STRIDE 36
#define WS_STRIDE 36

__global__ void __launch_bounds__(256, 2) proj_tc_kernel(
    const float* __restrict__ x,
    const float* __restrict__ Wk, const float* __restrict__ Wq,
    const float* __restrict__ Wv, const float* __restrict__ Wa,
    const float* __restrict__ b_alpha)
{
    __shared__ __align__(16) float Xs[TBM * XS_STRIDE];
    __shared__ __align__(16) float Ws[TBN * WS_STRIDE];

    const int tid = threadIdx.x;
    const int m0  = blockIdx.x * TBM;
    const int sel = blockIdx.y;
    const float* W = (sel == 0) ? Wk : (sel == 1) ? Wq : (sel == 2) ? Wv : Wa;

    const int warp  = tid >> 5;
    const int lane  = tid & 31;
    const int g     = lane >> 2;
    const int tg    = lane & 3;
    const int wm    = warp >> 1;
    const int wn    = warp & 1;
    const int am0   = wm * 32 + g;
    const int cn0   = wn * 32 + g;

    const int lr0 = tid >> 3;
    const int lc0 = (tid & 7) * 4;

    const float* xp = &x[(size_t)(m0 + lr0) * DIMK + lc0];
    const float* wp = &W[(size_t)lr0 * DIMK + lc0];

    float acc[2][4][4];
    #pragma unroll
    for (int mt = 0; mt < 2; mt++)
        #pragma unroll
        for (int nt = 0; nt < 4; nt++)
            #pragma unroll
            for (int j = 0; j < 4; j++) acc[mt][nt][j] = 0.f;

    float4 xr[4], wr[2];
    #pragma unroll
    for (int i = 0; i < 4; i++)
        xr[i] = *reinterpret_cast<const float4*>(xp + (size_t)i * 32 * DIMK);
    #pragma unroll
    for (int i = 0; i < 2; i++)
        wr[i] = *reinterpret_cast<const float4*>(wp + (size_t)i * 32 * DIMK);

    for (int k0 = 0; k0 < DIMK; k0 += TBK) {
        __syncthreads();
        #pragma unroll
        for (int i = 0; i < 4; i++)
            *reinterpret_cast<float4*>(&Xs[(lr0 + 32 * i) * XS_STRIDE + lc0]) = xr[i];
        #pragma unroll
        for (int i = 0; i < 2; i++)
            *reinterpret_cast<float4*>(&Ws[(lr0 + 32 * i) * WS_STRIDE + lc0]) = wr[i];
        __syncthreads();

        if (k0 + TBK < DIMK) {
            #pragma unroll
            for (int i = 0; i < 4; i++)
                xr[i] = *reinterpret_cast<const float4*>(xp + (size_t)i * 32 * DIMK + k0 + TBK);
            #pragma unroll
            for (int i = 0; i < 2; i++)
                wr[i] = *reinterpret_cast<const float4*>(wp + (size_t)i * 32 * DIMK + k0 + TBK);
        }

        #pragma unroll
        for (int ks = 0; ks < TBK / 8; ks++) {
            const int kk = ks * 8;

            uint32_t ah[2][4], al[2][4];
            #pragma unroll
            for (int mt = 0; mt < 2; mt++) {
                const int r0 = (am0 + mt * 16) * XS_STRIDE;
                const int r8 = (am0 + mt * 16 + 8) * XS_STRIDE;
                float a0 = Xs[r0 + kk + tg];
                float a1 = Xs[r8 + kk + tg];
                float a2 = Xs[r0 + kk + tg + 4];
                float a3 = Xs[r8 + kk + tg + 4];
                tf_split(a0, ah[mt][0], al[mt][0]);
                tf_split(a1, ah[mt][1], al[mt][1]);
                tf_split(a2, ah[mt][2], al[mt][2]);
                tf_split(a3, ah[mt][3], al[mt][3]);
            }
            uint32_t bh[4][2], bl[4][2];
            #pragma unroll
            for (int nt = 0; nt < 4; nt++) {
                const int c0 = (cn0 + nt * 8) * WS_STRIDE;
                float b0 = Ws[c0 + kk + tg];
                float b1 = Ws[c0 + kk + tg + 4];
                tf_split(b0, bh[nt][0], bl[nt][0]);
                tf_split(b1, bh[nt][1], bl[nt][1]);
            }
            #pragma unroll
            for (int mt = 0; mt < 2; mt++)
                #pragma unroll
                for (int nt = 0; nt < 4; nt++) {
                    mma_tf32(acc[mt][nt], ah[mt], bh[nt]);
                    mma_tf32(acc[mt][nt], al[mt], bh[nt]);
                    mma_tf32(acc[mt][nt], ah[mt], bl[nt]);
                }
        }
    }

    #pragma unroll
    for (int mt = 0; mt < 2; mt++) {
        #pragma unroll
        for (int nt = 0; nt < 4; nt++) {
            const int row = m0 + wm * 32 + mt * 16 + g;
            const int col = wn * 32 + nt * 8 + 2 * tg;
            float c0 = acc[mt][nt][0], c1 = acc[mt][nt][1];
            float c2 = acc[mt][nt][2], c3 = acc[mt][nt][3];
            if (sel == 3) {
                const float ba0 = b_alpha[col], ba1 = b_alpha[col + 1];
                c0 = sigmoidf_fast(c0 + ba0); c1 = sigmoidf_fast(c1 + ba1);
                c2 = sigmoidf_fast(c2 + ba0); c3 = sigmoidf_fast(c3 + ba1);
            }
            *reinterpret_cast<float2*>(&g_proj[(size_t)row * NCOL + sel * 64 + col])
                = make_float2(c0, c1);
            *reinterpret_cast<float2*>(&g_proj[(size_t)(row + 8) * NCOL + sel * 64 + col])
                = make_float2(c2, c3);
        }
    }
}

// ============================================================================
// Kernel 2: Gram precompute. block = one (chunk, batch):
// G[j][t]=k_j.k_t, H[j][t]=k_j.q_t. 128 threads = 128 dots of 64.
// ============================================================================
__global__ void __launch_bounds__(128) gram_kernel()
{
    __shared__ __align__(16) float kq[CHUNK][128];
    const int cb = blockIdx.x;
    const int c  = cb >> 3;
    const int b  = cb & 7;
    const int tid = threadIdx.x;

    const int st  = tid >> 4;
    const int off = (tid & 15) * 8;
    const float* src = &g_proj[((size_t)(c * CHUNK + st) * BATCH + b) * NCOL + off];
    *reinterpret_cast<float4*>(&kq[st][off])     = *reinterpret_cast<const float4*>(src);
    *reinterpret_cast<float4*>(&kq[st][off + 4]) = *reinterpret_cast<const float4*>(src + 4);
    __syncthreads();

    const int m = tid >> 6;          // 0 = G, 1 = H
    const int j = (tid >> 3) & 7;
    const int t = tid & 7;
    const float* kj = &kq[j][0];
    const float* xt = &kq[t][m ? 64 : 0];
    float sum = 0.f;
    #pragma unroll
    for (int e = 0; e < 64; e += 4) {
        float4 kv = *reinterpret_cast<const float4*>(kj + e);
        float4 xv = *reinterpret_cast<const float4*>(xt + e);
        sum = __fmaf_rn(kv.x, xv.x, sum);
        sum = __fmaf_rn(kv.y, xv.y, sum);
        sum = __fmaf_rn(kv.z, xv.z, sum);
        sum = __fmaf_rn(kv.w, xv.w, sum);
    }
    g_gram[((size_t)b * NCHUNK + c) * 128 + m * 64 + j * 8 + t] = sum;
}

// ============================================================================
// Kernel 3: chunked scan (tanh chain), recurrence only.
// 16 lanes/row, 2 rows/warp, 256 blocks x 32 threads.
// Qr eliminated: 1/P[j+1] = R_j * (1/P8) via suffix products -> ONE rcp/chunk.
// ============================================================================
#define RS 4
#define SLOT_FLOATS (CHUNK * NCOL + 64)

__device__ __forceinline__ void fetch_chunk(
    const float* gp, const float* gram_b, uint32_t sbase, int cf, int slot, int lane)
{
    uint32_t dst = sbase + (uint32_t)(slot * SLOT_FLOATS) * 4u;
    #pragma unroll
    for (int st = 0; st < CHUNK; st++) {
        const float* src = gp + (size_t)(cf * CHUNK + st) * BATCH * NCOL + lane * 8;
        uint32_t d = dst + (uint32_t)(st * NCOL + lane * 8) * 4u;
        asm volatile(
            "cp.async.ca.shared.global [%0], [%1], 16;\n\t"
            "cp.async.ca.shared.global [%2], [%3], 16;\n\t"
            :: "r"(d), "l"(src), "r"(d + 16u), "l"(src + 4));
    }
    const float* gs = gram_b + (size_t)cf * 128 + lane * 2;
    uint32_t d2 = dst + (uint32_t)(CHUNK * NCOL + lane * 2) * 4u;
    asm volatile("cp.async.ca.shared.global [%0], [%1], 8;" :: "r"(d2), "l"(gs));
    asm volatile("cp.async.commit_group;");
}

__global__ void __launch_bounds__(32) scan_kernel(
    const float* __restrict__ S0,
    const float* __restrict__ d_g,
    const float* __restrict__ b_g,
    float* __restrict__ Sfin)    // [B,N,N]
{
    __shared__ __align__(16) float ring[RS][SLOT_FLOATS];

    const int bx   = blockIdx.x;          // 0..255
    const int b    = bx >> 5;
    const int rg   = bx & 31;
    const int lane = threadIdx.x;
    const int r_   = lane >> 4;
    const int c    = lane & 15;
    const int i    = rg * 2 + r_;

    const float hd = 0.5f * d_g[i];
    const float hb = 0.5f * b_g[i];

    const float* gp     = &g_proj[(size_t)b * NCOL];
    const float* gram_b = &g_gram[(size_t)b * NCHUNK * 128];
    const uint32_t sbase = (uint32_t)__cvta_generic_to_shared(&ring[0][0]);

    float2 s[2];
    {
        float4 v0 = *reinterpret_cast<const float4*>(
            &S0[(size_t)(b * NST + i) * NST + c * 4]);
        s[0] = make_float2(v0.x, v0.y); s[1] = make_float2(v0.z, v0.w);
    }

    #pragma unroll
    for (int d = 0; d < RS - 1; d++)
        fetch_chunk(gp, gram_b, sbase, d, d, lane);

    for (int ch = 0; ch < NCHUNK; ch++) {
        {
            int cf = ch + RS - 1;
            if (cf > NCHUNK - 1) cf = NCHUNK - 1;
            fetch_chunk(gp, gram_b, sbase, cf, (ch + RS - 1) & (RS - 1), lane);
        }
        asm volatile("cp.async.wait_group %0;" :: "n"(RS - 2));
        __syncwarp();

        const float* p = &ring[ch & (RS - 1)][0];

        *reinterpret_cast<float4*>(
            &g_state[(((size_t)b * NCHUNK + ch) * NST + i) * NST + c * 4])
            = make_float4(s[0].x, s[0].y, s[1].x, s[1].y);

        float A[8];
        #pragma unroll
        for (int t = 0; t < 8; t++) {
            float4 kv = *reinterpret_cast<const float4*>(p + t * NCOL + c * 4);
            float2 aa = f2mul(s[0], make_float2(kv.x, kv.y));
            aa = f2fma(s[1], make_float2(kv.z, kv.w), aa);
            A[t] = aa.x + aa.y;
        }
        #pragma unroll
        for (int t = 0; t < 8; t++) {
            A[t] += __shfl_xor_sync(0xffffffffu, A[t], 1);
            A[t] += __shfl_xor_sync(0xffffffffu, A[t], 2);
            A[t] += __shfl_xor_sync(0xffffffffu, A[t], 4);
            A[t] += __shfl_xor_sync(0xffffffffu, A[t], 8);
        }

        // ---- per-row scalars: prefix P, hdP, hcv; suffix-product Qr ----
        float P[9], hdP[8], hcv[8], alv[8];
        P[0] = 1.f;
        #pragma unroll
        for (int t = 0; t < 8; t++) {
            alv[t] = p[t * NCOL + 192 + i];
            float vv = p[t * NCOL + 128 + i];
            hcv[t] = 0.5f * (1.f - alv[t]) * vv;     // 0.5*(1-alpha)*v
            hdP[t] = hd * P[t];
            P[t + 1] = P[t] * alv[t];
        }
        float hcq[8];
        {
            float invP8;
            asm("rcp.approx.f32 %0, %1;" : "=f"(invP8) : "f"(P[8]));
            // hcq[j] = hcv[j] * R_j * invP8, R_j = prod_{u>j} alpha_u
            float Sacc = invP8;                      // R_7 = 1
            hcq[7] = hcv[7] * Sacc;
            #pragma unroll
            for (int j = 6; j >= 0; j--) {
                Sacc *= alv[j + 1];
                hcq[j] = hcv[j] * Sacc;
            }
        }

        // ---- serial chain (tanh): arg -> tanh -> w -> fanout ----
        const float* gG = p + CHUNK * NCOL;
        float w[8];
        #pragma unroll
        for (int j = 0; j < 8; j++) {
            float4 g0 = *reinterpret_cast<const float4*>(gG + j * 8);
            float4 g1 = *reinterpret_cast<const float4*>(gG + j * 8 + 4);
            const float gv[8] = { g0.x, g0.y, g0.z, g0.w, g1.x, g1.y, g1.z, g1.w };

            float th;
            asm("tanh.approx.f32 %0, %1;" : "=f"(th) : "f"(__fmaf_rn(hdP[j], A[j], hb)));
            float wj = __fmaf_rn(hcq[j], th, hcq[j]);
            w[j] = wj;
            #pragma unroll
            for (int t2 = j + 1; t2 < 8; t2++)
                A[t2] = __fmaf_rn(wj, gv[t2], A[t2]);
        }

        if (c == 0) {
            float* wp = &g_wp[(((size_t)b * NCHUNK + ch) * NST + i) * 16];
            reinterpret_cast<float4*>(wp)[0] = make_float4(w[0], w[1], w[2], w[3]);
            reinterpret_cast<float4*>(wp)[1] = make_float4(w[4], w[5], w[6], w[7]);
            reinterpret_cast<float4*>(wp)[2] = make_float4(P[1], P[2], P[3], P[4]);
            reinterpret_cast<float4*>(wp)[3] = make_float4(P[5], P[6], P[7], P[8]);
        }

        #pragma unroll
        for (int j = 0; j < 8; j++) {
            float4 kv = *reinterpret_cast<const float4*>(p + j * NCOL + c * 4);
            float2 wj2 = f2dup(w[j]);
            s[0] = f2fma(wj2, make_float2(kv.x, kv.y), s[0]);
            s[1] = f2fma(wj2, make_float2(kv.z, kv.w), s[1]);
        }
        {
            float2 P82 = f2dup(P[8]);
            s[0] = f2mul(P82, s[0]);
            s[1] = f2mul(P82, s[1]);
        }
    }

    *reinterpret_cast<float4*>(&Sfin[(size_t)(b * NST + i) * NST + c * 4])
        = make_float4(s[0].x, s[0].y, s[1].x, s[1].y);
}

// ============================================================================
// Kernel 4: outputs (fully parallel) + fused self-gate.
// ============================================================================
__global__ void __launch_bounds__(256) out_kernel(float* __restrict__ out)
{
    __shared__ __align__(16) float qs[4][CHUNK][64];
    __shared__ __align__(16) float Hs[4][64];

    const int grp = threadIdx.x >> 6;
    const int i   = threadIdx.x & 63;
    const int cb  = blockIdx.x * 4 + grp;
    const int c   = cb >> 3;
    const int b   = cb & 7;

    #pragma unroll
    for (int t = 0; t < CHUNK; t++)
        qs[grp][t][i] = g_proj[((size_t)(c * CHUNK + t) * BATCH + b) * NCOL + 64 + i];
    Hs[grp][i] = g_gram[((size_t)b * NCHUNK + c) * 128 + 64 + i];
    __syncthreads();

    float4 S[16];
    {
        const float4* sp = reinterpret_cast<const float4*>(
            &g_state[(((size_t)b * NCHUNK + c) * NST + i) * NST]);
        #pragma unroll
        for (int e = 0; e < 16; e++) S[e] = sp[e];
    }

    float sq[8];
    #pragma unroll
    for (int t = 0; t < 8; t++) {
        float sum = 0.f;
        #pragma unroll
        for (int e = 0; e < 16; e++) {
            float4 qv = *reinterpret_cast<const float4*>(&qs[grp][t][e * 4]);
            sum = __fmaf_rn(S[e].x, qv.x, sum);
            sum = __fmaf_rn(S[e].y, qv.y, sum);
            sum = __fmaf_rn(S[e].z, qv.z, sum);
            sum = __fmaf_rn(S[e].w, qv.w, sum);
        }
        sq[t] = sum;
    }

    float w[8], Pv[8];
    {
        const float4* wp = reinterpret_cast<const float4*>(
            &g_wp[(((size_t)b * NCHUNK + c) * NST + i) * 16]);
        float4 w0 = wp[0], w1 = wp[1], p0 = wp[2], p1 = wp[3];
        w[0] = w0.x; w[1] = w0.y; w[2] = w0.z; w[3] = w0.w;
        w[4] = w1.x; w[5] = w1.y; w[6] = w1.z; w[7] = w1.w;
        Pv[0] = p0.x; Pv[1] = p0.y; Pv[2] = p0.z; Pv[3] = p0.w;
        Pv[4] = p1.x; Pv[5] = p1.y; Pv[6] = p1.z; Pv[7] = p1.w;
    }

    #pragma unroll
    for (int t = 0; t < 8; t++) {
        float a = sq[t];
        #pragma unroll
        for (int j = 0; j <= t; j++)
            a = __fmaf_rn(w[j], Hs[grp][j * 8 + t], a);
        float o = Pv[t] * a;
        float y = o * o * sigmoidf_fast(o);
        out[((size_t)(c * CHUNK + t) * BATCH + b) * NST + i] = y;
    }
}

// ============================================================================
extern "C" void kernel_launch(void* const* d_in, const int* in_sizes, int n_in,
                              void* d_out, int out_size) {
    const float* x   = (const float*)d_in[0];
    const float* S0  = (const float*)d_in[1];
    const float* Wk  = (const float*)d_in[2];
    const float* Wv  = (const float*)d_in[3];
    const float* Wq  = (const float*)d_in[4];
    const float* Wa  = (const float*)d_in[5];
    const float* ba  = (const float*)d_in[6];
    const float* dg  = (const float*)d_in[7];
    const float* bg  = (const float*)d_in[8];

    float* out  = (float*)d_out;                         // [T,B,N]
    float* Sfin = out + (size_t)T_STEPS * BATCH * NST;   // [B,N,N]

    dim3 g1(M_ROWS / TBM, 4);
    proj_tc_kernel<<<g1, 256>>>(x, Wk, Wq, Wv, Wa, ba);
    gram_kernel<<<NCHUNK * BATCH, 128>>>();
    scan_kernel<<<256, 32>>>(S0, dg, bg, Sfin);
    out_kernel<<<NCHUNK * BATCH / 4, 256>>>(out);
}